// round 15
// baseline (speedup 1.0000x reference)
#include <cuda_runtime.h>
#include <cuda_bf16.h>
#include <math.h>
#include <stdint.h>

#define BB 32
#define TT 512
#define EE 256
#define UU 512
#define U3 1536
#define NBLK 64          // blocks per direction
#define RGRID (2*NBLK)
#define HSTR 520         // h SMEM ushort stride (260 words, mod32=4)
#define XSTR 264         // x SMEM ushort stride (132 words, mod32=4)
#define BSTR 776         // B SMEM ushort stride (388 words, mod32=4)
#define PSR  34          // psum row stride (floats, EVEN for float2 alignment)

// ---------------- device scratch ---------------------------------------------
__device__ unsigned short g_embh[(size_t)32000 * EE];
__device__ unsigned short g_embl[(size_t)32000 * EE];
__device__ int            g_tokT[TT * BB];
__device__ unsigned short g_hh[2][2][BB][UU];
__device__ unsigned short g_hl[2][2][BB][UU];
__device__ unsigned       g_cnt[2][TT];

// ---------------- bf16 split helpers -----------------------------------------
__device__ __forceinline__ unsigned short bf16_hi(float v) {
    return __bfloat16_as_ushort(__float2bfloat16_rn(v));
}
__device__ __forceinline__ void split2(float v, unsigned short& h, unsigned short& l) {
    h = bf16_hi(v);
    float fh = __uint_as_float((unsigned)h << 16);
    l = bf16_hi(v - fh);
}
__device__ __forceinline__ float joinhl(unsigned short h, unsigned short l) {
    return __uint_as_float((unsigned)h << 16) + __uint_as_float((unsigned)l << 16);
}

// ---------------- bf16 mma (m16n8k16) -----------------------------------------
__device__ __forceinline__ void mma_bf16(float* D,
                                         unsigned a0, unsigned a1, unsigned a2, unsigned a3,
                                         unsigned b0, unsigned b1) {
    asm volatile(
        "mma.sync.aligned.m16n8k16.row.col.f32.bf16.bf16.f32 "
        "{%0,%1,%2,%3}, {%4,%5,%6,%7}, {%8,%9}, {%0,%1,%2,%3};"
        : "+f"(D[0]), "+f"(D[1]), "+f"(D[2]), "+f"(D[3])
        : "r"(a0), "r"(a1), "r"(a2), "r"(a3), "r"(b0), "r"(b1));
}

// ---------------- prep: split emb to bf16 hi/lo + transpose tokens -----------
__global__ void __launch_bounds__(256) prep_kernel(
    const int* __restrict__ tokens, const float* __restrict__ emb)
{
    int gid = blockIdx.x * 256 + threadIdx.x;
    size_t base = (size_t)gid * 4;
    float4 v = *(const float4*)(emb + base);
    unsigned short h, l;
    split2(v.x, h, l); g_embh[base+0] = h; g_embl[base+0] = l;
    split2(v.y, h, l); g_embh[base+1] = h; g_embl[base+1] = l;
    split2(v.z, h, l); g_embh[base+2] = h; g_embl[base+2] = l;
    split2(v.w, h, l); g_embh[base+3] = h; g_embl[base+3] = l;
    if (gid < BB * TT) {
        int b = gid >> 9, t = gid & 511;
        g_tokT[t * 32 + b] = tokens[gid];
    }
}

// ---------------- fused persistent GRU ---------------------------------------
// 128 blocks (64/dir), 256 threads = 8 warps (2 m-tiles x 4 k-splits).
// Per step: P[32x32cols] = [x(t)(k<256) || h(t-1)(k>=256)] * B(768x32), where
// cols 0-7=z(W+U), 8-15=r(W+U), 16-23=xh(W only), 24-31=hh(U only).
// x-part MMAs: n-tiles {0,1,2}; h-part MMAs: n-tiles {0,1,3}.
#define SMEM_BYTES ((32*HSTR + 32*XSTR + 32*BSTR) * 2 * 2 + 3*32*PSR*4)

__global__ void __launch_bounds__(256, 1) gru_kernel(
    const float* __restrict__ W_fw, const float* __restrict__ b_in_fw,
    const float* __restrict__ b_rec_fw,
    const float* __restrict__ W_bw, const float* __restrict__ b_in_bw,
    const float* __restrict__ b_rec_bw,
    const float* __restrict__ U_fw, const float* __restrict__ U_bw,
    float* __restrict__ out)
{
    extern __shared__ unsigned short smemus[];
    unsigned short* hsH = smemus;               // [32][520]
    unsigned short* hsL = hsH + 32*HSTR;
    unsigned short* xAH = hsL + 32*HSTR;        // [32][264]
    unsigned short* xAL = xAH + 32*XSTR;
    unsigned short* BH  = xAL + 32*XSTR;        // [32][776] rows k<256=W-part
    unsigned short* BL  = BH + 32*BSTR;
    float* psum = (float*)(BL + 32*BSTR);       // [3][32][PSR]

    unsigned* hsHw = (unsigned*)hsH;
    unsigned* hsLw = (unsigned*)hsL;
    unsigned* xAHw = (unsigned*)xAH;
    unsigned* xALw = (unsigned*)xAL;
    const unsigned* BHw = (const unsigned*)BH;
    const unsigned* BLw = (const unsigned*)BL;

    const int bid = blockIdx.x;
    const int d   = bid >> 6;
    const int jb  = bid & (NBLK - 1);
    const int u0  = jb * 8;
    const int tid = threadIdx.x;
    const int lane = tid & 31;
    const int wid = tid >> 5;
    const int mi = wid & 1;
    const int kh = wid >> 1;
    const int gr = lane >> 2;
    const int gc = lane & 3;

    const float* __restrict__ Wp = d ? W_bw : W_fw;
    const float* __restrict__ Uw = d ? U_bw : U_fw;
    const float* __restrict__ bi = d ? b_in_bw : b_in_fw;
    const float* __restrict__ br = d ? b_rec_bw : b_rec_fw;

    // ---- stage B (32 cols x 768 rows) hi/lo once ----
    for (int idx = tid; idx < 32 * 768; idx += 256) {
        int c = idx / 768;
        int k = idx - c * 768;
        int grp = c >> 3;                 // 0..3
        int uu  = u0 + (c & 7);
        float v;
        if (grp == 0)      v = (k < 256) ? Wp[(size_t)k * U3 + uu]
                                         : Uw[(size_t)(k-256) * U3 + uu];
        else if (grp == 1) v = (k < 256) ? Wp[(size_t)k * U3 + 512 + uu]
                                         : Uw[(size_t)(k-256) * U3 + 512 + uu];
        else if (grp == 2) v = (k < 256) ? Wp[(size_t)k * U3 + 1024 + uu] : 0.f;
        else               v = (k < 256) ? 0.f : Uw[(size_t)(k-256) * U3 + 1024 + uu];
        unsigned short h, l;
        split2(v, h, l);
        BH[c * BSTR + k] = h;
        BL[c * BSTR + k] = l;
    }

    // epilogue constants
    const int eb = tid >> 3, eu = tid & 7;
    const float bz  = bi[0*512 + u0 + eu] + br[0*512 + u0 + eu];
    const float brg = bi[1*512 + u0 + eu] + br[1*512 + u0 + eu];
    const float bih = bi[2*512 + u0 + eu];
    const float brh = br[2*512 + u0 + eu];

    const int base0 = (mi*16 + gr) * (HSTR/2);
    const int base1 = base0 + 8 * (HSTR/2);
    const int xb0   = (mi*16 + gr) * (XSTR/2);
    const int xb1   = xb0 + 8 * (XSTR/2);
    const int r0  = mi*16 + gr;
    const int r1  = r0 + 8;
    const int kwbase  = kh * 64;
    const int xkwbase = kh * 32;
    const int srow = mi * 16;
    const int sk8  = kh * 16;

    __syncthreads();

    for (int ts = 0; ts < TT; ts++) {
        const int t   = d ? (TT - 1 - ts) : ts;
        const int buf = ts & 1;

        // ---- stage x(t) slab BEFORE barrier wait (hidden in spin window) ---
#pragma unroll
        for (int i = 0; i < 4; i++) {
            int uid  = lane + 32 * i;            // 0..127
            int row  = srow + (uid >> 3);
            int slot = uid & 7;
            int tok  = g_tokT[t * 32 + row];
            uint4 vH = __ldg((const uint4*)(g_embh + (size_t)tok * EE + kh * 64) + slot);
            uint4 vL = __ldg((const uint4*)(g_embl + (size_t)tok * EE + kh * 64) + slot);
            *(uint4*)(xAHw + row * (XSTR/2) + xkwbase + slot * 4) = vH;
            *(uint4*)(xALw + row * (XSTR/2) + xkwbase + slot * 4) = vL;
        }
        int mt = (g_tokT[t * 32 + eb] != 0);

        // ---- wait for previous step (direction-local) ----
        if (ts) {
            if (tid == 0) {
                volatile unsigned* c = &g_cnt[d][ts - 1];
                while (*c < NBLK) { }
                __threadfence();
            }
            __syncthreads();
        }

        // ---- warp-local h staging ----
#pragma unroll
        for (int i = 0; i < 8; i++) {
            int uid = lane + 32 * i;
            int row = srow + (uid >> 4);
            int col = uid & 15;
            uint4 vH = __ldcg((const uint4*)&g_hh[d][buf][row][0] + sk8 + col);
            uint4 vL = __ldcg((const uint4*)&g_hl[d][buf][row][0] + sk8 + col);
            *(uint4*)(hsHw + row * (HSTR/2) + kwbase + col * 4) = vH;
            *(uint4*)(hsLw + row * (HSTR/2) + kwbase + col * 4) = vL;
        }
        __syncwarp();

        // ---- bf16x3 dot: 4 n-tiles, x-part {0,1,2}, h-part {0,1,3} ----
        float Dhh[4][4], Dhl[4][4], Dlh[4][4];
#pragma unroll
        for (int j = 0; j < 4; j++)
#pragma unroll
            for (int q = 0; q < 4; q++) { Dhh[j][q]=0.f; Dhl[j][q]=0.f; Dlh[j][q]=0.f; }

        // x part: B rows k<256 (word offsets 0..127)
#pragma unroll
        for (int kt = 0; kt < 4; kt++) {
            int kw = xkwbase + kt * 8;
            unsigned ah0 = xAHw[xb0 + kw + gc];
            unsigned ah1 = xAHw[xb1 + kw + gc];
            unsigned ah2 = xAHw[xb0 + kw + gc + 4];
            unsigned ah3 = xAHw[xb1 + kw + gc + 4];
            unsigned al0 = xALw[xb0 + kw + gc];
            unsigned al1 = xALw[xb1 + kw + gc];
            unsigned al2 = xALw[xb0 + kw + gc + 4];
            unsigned al3 = xALw[xb1 + kw + gc + 4];
#pragma unroll
            for (int j = 0; j < 3; j++) {
                int ub = (j*8 + gr) * (BSTR/2) + kw + gc;
                unsigned bh0 = BHw[ub], bh1 = BHw[ub + 4];
                unsigned bl0 = BLw[ub], bl1 = BLw[ub + 4];
                mma_bf16(Dhh[j], ah0, ah1, ah2, ah3, bh0, bh1);
                mma_bf16(Dhl[j], ah0, ah1, ah2, ah3, bl0, bl1);
                mma_bf16(Dlh[j], al0, al1, al2, al3, bh0, bh1);
            }
        }
        // h part: B rows k>=256 (word offset 128+), n-tiles 0,1,3
#pragma unroll 2
        for (int kt = 0; kt < 8; kt++) {
            int kw = kwbase + kt * 8;
            unsigned ah0 = hsHw[base0 + kw + gc];
            unsigned ah1 = hsHw[base1 + kw + gc];
            unsigned ah2 = hsHw[base0 + kw + gc + 4];
            unsigned ah3 = hsHw[base1 + kw + gc + 4];
            unsigned al0 = hsLw[base0 + kw + gc];
            unsigned al1 = hsLw[base1 + kw + gc];
            unsigned al2 = hsLw[base0 + kw + gc + 4];
            unsigned al3 = hsLw[base1 + kw + gc + 4];
#pragma unroll
            for (int jj = 0; jj < 3; jj++) {
                int j = (jj == 2) ? 3 : jj;
                int ub = (j*8 + gr) * (BSTR/2) + 128 + kw + gc;
                unsigned bh0 = BHw[ub], bh1 = BHw[ub + 4];
                unsigned bl0 = BLw[ub], bl1 = BLw[ub + 4];
                mma_bf16(Dhh[j], ah0, ah1, ah2, ah3, bh0, bh1);
                mma_bf16(Dhl[j], ah0, ah1, ah2, ah3, bl0, bl1);
                mma_bf16(Dlh[j], al0, al1, al2, al3, bh0, bh1);
            }
        }

        float D[4][4];
#pragma unroll
        for (int j = 0; j < 4; j++)
#pragma unroll
            for (int q = 0; q < 4; q++)
                D[j][q] = Dhh[j][q] + Dhl[j][q] + Dlh[j][q];

        // ---- two-phase k-split reduction (4 n-tiles, EVEN stride PSR) ----
        if (kh > 0) {
#pragma unroll
            for (int j = 0; j < 4; j++) {
                int cc = j*8 + gc*2;
                *(float2*)&psum[((kh-1)*32 + r0)*PSR + cc] = make_float2(D[j][0], D[j][1]);
                *(float2*)&psum[((kh-1)*32 + r1)*PSR + cc] = make_float2(D[j][2], D[j][3]);
            }
        }
        __syncthreads();
        if (kh == 0) {
#pragma unroll
            for (int s = 0; s < 3; s++)
#pragma unroll
                for (int j = 0; j < 4; j++) {
                    int cc = j*8 + gc*2;
                    float2 p0 = *(const float2*)&psum[(s*32 + r0)*PSR + cc];
                    float2 p1 = *(const float2*)&psum[(s*32 + r1)*PSR + cc];
                    D[j][0] += p0.x; D[j][1] += p0.y;
                    D[j][2] += p1.x; D[j][3] += p1.y;
                }
#pragma unroll
            for (int j = 0; j < 4; j++) {
                int cc = j*8 + gc*2;
                *(float2*)&psum[r0*PSR + cc] = make_float2(D[j][0], D[j][1]);
                *(float2*)&psum[r1*PSR + cc] = make_float2(D[j][2], D[j][3]);
            }
        }
        __syncthreads();

        // ---- epilogue ----
        {
            float az = psum[eb*PSR + 0  + eu] + bz;
            float ar = psum[eb*PSR + 8  + eu] + brg;
            float xh = psum[eb*PSR + 16 + eu] + bih;
            float hh = psum[eb*PSR + 24 + eu] + brh;

            float z    = __fdividef(1.f, 1.f + __expf(-az));
            float r    = __fdividef(1.f, 1.f + __expf(-ar));
            float ta   = xh + r * hh;
            float cand = 1.f - __fdividef(2.f, __expf(2.f * ta) + 1.f);
            float hp   = joinhl(hsH[eb * HSTR + u0 + eu], hsL[eb * HSTR + u0 + eu]);
            float hn   = z * hp + (1.f - z) * cand;
            if (!mt) hn = hp;

            unsigned short hnh, hnl;
            split2(hn, hnh, hnl);
            g_hh[d][buf ^ 1][eb][u0 + eu] = hnh;
            g_hl[d][buf ^ 1][eb][u0 + eu] = hnl;
            out[((size_t)eb * TT + t) * (2*UU) + (size_t)d * UU + u0 + eu] = hn;
        }

        // ---- arrive ----
        if (ts + 1 < TT) {
            __syncthreads();
            if (tid == 0) { __threadfence(); atomicAdd(&g_cnt[d][ts], 1u); }
        }
    }
}

// ---------------- launch ------------------------------------------------------
extern "C" void kernel_launch(void* const* d_in, const int* in_sizes, int n_in,
                              void* d_out, int out_size)
{
    const int*   tokens   = (const int*)  d_in[0];
    const float* emb      = (const float*)d_in[1];
    const float* W_fw     = (const float*)d_in[2];
    const float* U_fw     = (const float*)d_in[3];
    const float* b_in_fw  = (const float*)d_in[4];
    const float* b_rec_fw = (const float*)d_in[5];
    const float* W_bw     = (const float*)d_in[6];
    const float* U_bw     = (const float*)d_in[7];
    const float* b_in_bw  = (const float*)d_in[8];
    const float* b_rec_bw = (const float*)d_in[9];
    float* out = (float*)d_out;

    void* p;
    cudaGetSymbolAddress(&p, g_hh);
    cudaMemsetAsync(p, 0, sizeof(g_hh));
    cudaGetSymbolAddress(&p, g_hl);
    cudaMemsetAsync(p, 0, sizeof(g_hl));
    cudaGetSymbolAddress(&p, g_cnt);
    cudaMemsetAsync(p, 0, sizeof(g_cnt));

    prep_kernel<<<8000, 256>>>(tokens, emb);

    cudaFuncSetAttribute(gru_kernel,
                         cudaFuncAttributeMaxDynamicSharedMemorySize, SMEM_BYTES);
    gru_kernel<<<RGRID, 256, SMEM_BYTES>>>(W_fw, b_in_fw, b_rec_fw,
                                           W_bw, b_in_bw, b_rec_bw,
                                           U_fw, U_bw, out);
}

// round 16
// speedup vs baseline: 1.2532x; 1.2532x over previous
#include <cuda_runtime.h>
#include <cuda_bf16.h>
#include <math.h>
#include <stdint.h>

#define BB 32
#define TT 512
#define EE 256
#define UU 512
#define U3 1536
#define NBLK 64
#define RGRID (2*NBLK)
#define HSTR 520         // gru SMEM ushort stride
#define ASTR 40          // xproj SMEM ushort stride (20 words)

// ---------------- device scratch ---------------------------------------------
__device__ unsigned short g_embh[(size_t)32000 * EE];
__device__ unsigned short g_embl[(size_t)32000 * EE];
__device__ unsigned short g_WTh[2][(size_t)U3 * EE];   // W^T split hi [d][n][k]
__device__ unsigned short g_WTl[2][(size_t)U3 * EE];   // W^T split lo
__device__ int            g_tokT[TT * BB];
__device__ unsigned short g_hh[2][2][BB][UU];
__device__ unsigned short g_hl[2][2][BB][UU];
__device__ unsigned       g_cnt[2][TT];
__device__ float          g_xproj[2][BB][TT][U3];

// ---------------- bf16 helpers -------------------------------------------------
__device__ __forceinline__ unsigned short bf16_hi(float v) {
    return __bfloat16_as_ushort(__float2bfloat16_rn(v));
}
__device__ __forceinline__ void split2(float v, unsigned short& h, unsigned short& l) {
    h = bf16_hi(v);
    float fh = __uint_as_float((unsigned)h << 16);
    l = bf16_hi(v - fh);
}
__device__ __forceinline__ float joinhl(unsigned short h, unsigned short l) {
    return __uint_as_float((unsigned)h << 16) + __uint_as_float((unsigned)l << 16);
}
__device__ __forceinline__ void mma_bf16(float* D,
                                         unsigned a0, unsigned a1, unsigned a2, unsigned a3,
                                         unsigned b0, unsigned b1) {
    asm volatile(
        "mma.sync.aligned.m16n8k16.row.col.f32.bf16.bf16.f32 "
        "{%0,%1,%2,%3}, {%4,%5,%6,%7}, {%8,%9}, {%0,%1,%2,%3};"
        : "+f"(D[0]), "+f"(D[1]), "+f"(D[2]), "+f"(D[3])
        : "r"(a0), "r"(a1), "r"(a2), "r"(a3), "r"(b0), "r"(b1));
}
__device__ __forceinline__ void cp16(void* dst, const void* src) {
    unsigned daddr = (unsigned)__cvta_generic_to_shared(dst);
    asm volatile("cp.async.cg.shared.global [%0], [%1], 16;" :: "r"(daddr), "l"(src));
}

// ---------------- prep 1: split emb + transpose tokens -------------------------
__global__ void __launch_bounds__(256) prep_kernel(
    const int* __restrict__ tokens, const float* __restrict__ emb)
{
    int gid = blockIdx.x * 256 + threadIdx.x;
    size_t base = (size_t)gid * 4;
    float4 v = *(const float4*)(emb + base);
    unsigned short h, l;
    split2(v.x, h, l); g_embh[base+0] = h; g_embl[base+0] = l;
    split2(v.y, h, l); g_embh[base+1] = h; g_embl[base+1] = l;
    split2(v.z, h, l); g_embh[base+2] = h; g_embl[base+2] = l;
    split2(v.w, h, l); g_embh[base+3] = h; g_embl[base+3] = l;
    if (gid < BB * TT) {
        int b = gid >> 9, t = gid & 511;
        g_tokT[t * 32 + b] = tokens[gid];
    }
}

// ---------------- prep 2: split + transpose W -----------------------------------
__global__ void __launch_bounds__(256) wprep_kernel(
    const float* __restrict__ W_fw, const float* __restrict__ W_bw)
{
    int gid = blockIdx.x * 256 + threadIdx.x;          // < 2*256*1536
    int d = gid / (EE * U3);
    int r = gid - d * (EE * U3);
    int k = r / U3;
    int n = r - k * U3;
    float v = (d ? W_bw : W_fw)[r];
    unsigned short h, l;
    split2(v, h, l);
    g_WTh[d][(size_t)n * EE + k] = h;
    g_WTl[d][(size_t)n * EE + k] = l;
}

// ---------------- Kernel A: xproj, cp.async double-buffered bf16x3 GEMM --------
// block 256 thr = 8 warps; BM=128, BN=64, BK=32, 8 k-iters, 2-stage pipeline.
#define XP_SMEM ((2*128*ASTR + 2*128*ASTR/1 /*A hi+lo*/) * 0 + (2*5120*2 + 2*2560*2) * 2)
// A: 2 bufs x 128 x 40 ushorts per array (hi, lo) = 2*5120 each
// B: 2 bufs x  64 x 40 ushorts per array           = 2*2560 each
#define XSMEM_USH (2*5120*2 + 2*2560*2)
#define XSMEM_BYTES (XSMEM_USH * 2)

__global__ void __launch_bounds__(256) xproj_kernel(
    const int* __restrict__ tokens,
    const float* __restrict__ b_in_fw, const float* __restrict__ b_in_bw,
    float* __restrict__ gx)
{
    extern __shared__ unsigned short xs[];
    unsigned short* SAh = xs;                   // [2][128*40]
    unsigned short* SAl = SAh + 2*5120;
    unsigned short* SBh = SAl + 2*5120;         // [2][64*40]
    unsigned short* SBl = SBh + 2*2560;
    __shared__ int toks[128];

    const int d  = blockIdx.z;
    const float* __restrict__ bp = d ? b_in_bw : b_in_fw;
    const unsigned short* WTh = g_WTh[d];
    const unsigned short* WTl = g_WTl[d];
    const int n0 = blockIdx.x * 64;
    const int m0 = blockIdx.y * 128;
    const int tid = threadIdx.x;
    const int wid = tid >> 5;
    const int lane = tid & 31;
    const int gr = lane >> 2;
    const int gc = lane & 3;

    if (tid < 128) toks[tid] = tokens[m0 + tid];
    __syncthreads();

    const unsigned* SAhw = (const unsigned*)SAh;
    const unsigned* SAlw = (const unsigned*)SAl;
    const unsigned* SBhw = (const unsigned*)SBh;
    const unsigned* SBlw = (const unsigned*)SBl;

    float D[8][4];
#pragma unroll
    for (int j = 0; j < 8; j++)
#pragma unroll
        for (int q = 0; q < 4; q++) D[j][q] = 0.f;

    const int baseA0 = (wid * 16 + gr) * (ASTR/2);
    const int baseA1 = baseA0 + 8 * (ASTR/2);

    // ---- staging lambda (cp.async): buffer bf, k offset k0 ----
    auto stage = [&](int bf, int k0) {
        int ao = bf * 5120, bo = bf * 2560;
#pragma unroll
        for (int i = 0; i < 4; i++) {
            int uid = tid + i * 256;             // 0..1023
            int row = uid >> 3;
            int rem = uid & 7;
            int arr = rem >> 2;
            int ch  = rem & 3;
            const unsigned short* src =
                (arr ? g_embl : g_embh) + (size_t)toks[row] * EE + k0 + ch * 8;
            unsigned short* dst =
                (arr ? SAl : SAh) + ao + row * ASTR + ch * 8;
            cp16(dst, src);
        }
#pragma unroll
        for (int i = 0; i < 2; i++) {
            int uid = tid + i * 256;             // 0..511
            int col = uid >> 3;
            int rem = uid & 7;
            int arr = rem >> 2;
            int ch  = rem & 3;
            const unsigned short* src =
                (arr ? WTl : WTh) + (size_t)(n0 + col) * EE + k0 + ch * 8;
            unsigned short* dst =
                (arr ? SBl : SBh) + bo + col * ASTR + ch * 8;
            cp16(dst, src);
        }
        asm volatile("cp.async.commit_group;" ::: "memory");
    };

    stage(0, 0);

    for (int it = 0; it < 8; it++) {
        if (it < 7) {
            stage((it + 1) & 1, (it + 1) * 32);
            asm volatile("cp.async.wait_group 1;" ::: "memory");
        } else {
            asm volatile("cp.async.wait_group 0;" ::: "memory");
        }
        __syncthreads();

        const int aw = (it & 1) * 2560;          // word offset (5120 ushorts / 2)
        const int bw = (it & 1) * 1280;
#pragma unroll
        for (int kt = 0; kt < 2; kt++) {
            int kw = kt * 8;
            unsigned ah0 = SAhw[aw + baseA0 + kw + gc];
            unsigned ah1 = SAhw[aw + baseA1 + kw + gc];
            unsigned ah2 = SAhw[aw + baseA0 + kw + gc + 4];
            unsigned ah3 = SAhw[aw + baseA1 + kw + gc + 4];
            unsigned al0 = SAlw[aw + baseA0 + kw + gc];
            unsigned al1 = SAlw[aw + baseA1 + kw + gc];
            unsigned al2 = SAlw[aw + baseA0 + kw + gc + 4];
            unsigned al3 = SAlw[aw + baseA1 + kw + gc + 4];
#pragma unroll
            for (int j = 0; j < 8; j++) {
                int ub = bw + (j * 8 + gr) * (ASTR/2) + kw + gc;
                unsigned bh0 = SBhw[ub], bh1 = SBhw[ub + 4];
                unsigned bl0 = SBlw[ub], bl1 = SBlw[ub + 4];
                mma_bf16(D[j], ah0, ah1, ah2, ah3, bh0, bh1);
                mma_bf16(D[j], ah0, ah1, ah2, ah3, bl0, bl1);
                mma_bf16(D[j], al0, al1, al2, al3, bh0, bh1);
            }
        }
        __syncthreads();
    }

    const size_t mbase = (size_t)d * (BB*TT) + m0 + wid * 16;
#pragma unroll
    for (int j = 0; j < 8; j++) {
        int cc = n0 + j * 8 + gc * 2;
        float2 bias = *(const float2*)(bp + cc);
        float2 vlo = { D[j][0] + bias.x, D[j][1] + bias.y };
        float2 vhi = { D[j][2] + bias.x, D[j][3] + bias.y };
        *(float2*)(gx + (mbase + gr)     * U3 + cc) = vlo;
        *(float2*)(gx + (mbase + gr + 8) * U3 + cc) = vhi;
    }
}

// ---------------- Kernel B: persistent GRU (R11/R13 verified, verbatim) --------
#define SMEM_R11 ((32*HSTR*2 + 24*HSTR*2) * 2 + 3*32*24*4 + 64)

__global__ void __launch_bounds__(256, 1) gru_r11(
    const float* __restrict__ U_fw, const float* __restrict__ b_rec_fw,
    const float* __restrict__ U_bw, const float* __restrict__ b_rec_bw,
    float* __restrict__ out)
{
    extern __shared__ unsigned short smemus[];
    unsigned short* hsH = smemus;
    unsigned short* hsL = hsH + 32*HSTR;
    unsigned short* UsH = hsL + 32*HSTR;
    unsigned short* UsL = UsH + 24*HSTR;
    float* psum = (float*)(UsL + 24*HSTR);

    const unsigned* hsHw = (const unsigned*)hsH;
    const unsigned* hsLw = (const unsigned*)hsL;
    const unsigned* UsHw = (const unsigned*)UsH;
    const unsigned* UsLw = (const unsigned*)UsL;

    const int bid = blockIdx.x;
    const int d   = bid >> 6;
    const int jb  = bid & (NBLK - 1);
    const int u0  = jb * 8;
    const int tid = threadIdx.x;
    const int wid = tid >> 5;
    const int lane = tid & 31;
    const int mi = wid & 1;
    const int kh = wid >> 1;
    const int gr = lane >> 2;
    const int gc = lane & 3;

    const float* __restrict__ Uw = d ? U_bw : U_fw;
    const float* __restrict__ br = d ? b_rec_bw : b_rec_fw;

    for (int idx = tid; idx < 24 * 512; idx += 256) {
        int c = idx >> 9;
        int k = idx & 511;
        int g = c >> 3;
        float v = Uw[(size_t)k * U3 + g * 512 + u0 + (c & 7)];
        unsigned short h, l;
        split2(v, h, l);
        UsH[c * HSTR + k] = h;
        UsL[c * HSTR + k] = l;
    }

    const int eb = tid >> 3, eu = tid & 7;
    const float brz = br[0*512 + u0 + eu];
    const float brr = br[1*512 + u0 + eu];
    const float brh = br[2*512 + u0 + eu];

    const float* gx = &g_xproj[0][0][0][0];

    const int base0 = (mi*16 + gr) * (HSTR/2);
    const int base1 = base0 + 8 * (HSTR/2);
    const int r0  = mi*16 + gr;
    const int r1  = r0 + 8;
    const int kwbase = kh * 64;
    const int srow = mi * 16;
    const int sk   = kh * 128;

    __syncthreads();

    for (int ts = 0; ts < TT; ts++) {
        const int t   = d ? (TT - 1 - ts) : ts;
        const int buf = ts & 1;

        size_t xb = ((size_t)d * (BB*TT) + (size_t)eb * TT + t) * U3;
        float xz = gx[xb + u0 + eu];
        float xr = gx[xb + 512 + u0 + eu];
        float xh = gx[xb + 1024 + u0 + eu];
        int   mt = (g_tokT[t * 32 + eb] != 0);

#pragma unroll
        for (int i = 0; i < 8; i++) {
            int uid = lane + 32 * i;
            int row = srow + (uid >> 4);
            int col = uid & 15;
            uint4 vH = __ldcg((const uint4*)&g_hh[d][buf][row][sk] + col);
            uint4 vL = __ldcg((const uint4*)&g_hl[d][buf][row][sk] + col);
            *(uint4*)&hsH[row * HSTR + sk + col * 8] = vH;
            *(uint4*)&hsL[row * HSTR + sk + col * 8] = vL;
        }
        __syncwarp();

        float Dhh[3][4], Dhl[3][4], Dlh[3][4];
#pragma unroll
        for (int j = 0; j < 3; j++)
#pragma unroll
            for (int q = 0; q < 4; q++) { Dhh[j][q] = 0.f; Dhl[j][q] = 0.f; Dlh[j][q] = 0.f; }

#pragma unroll 2
        for (int kt = 0; kt < 8; kt++) {
            int kw = kwbase + kt * 8;
            unsigned ah0 = hsHw[base0 + kw + gc];
            unsigned ah1 = hsHw[base1 + kw + gc];
            unsigned ah2 = hsHw[base0 + kw + gc + 4];
            unsigned ah3 = hsHw[base1 + kw + gc + 4];
            unsigned al0 = hsLw[base0 + kw + gc];
            unsigned al1 = hsLw[base1 + kw + gc];
            unsigned al2 = hsLw[base0 + kw + gc + 4];
            unsigned al3 = hsLw[base1 + kw + gc + 4];
#pragma unroll
            for (int j = 0; j < 3; j++) {
                int ub = (j*8 + gr) * (HSTR/2) + kw + gc;
                unsigned bh0 = UsHw[ub], bh1 = UsHw[ub + 4];
                unsigned bl0 = UsLw[ub], bl1 = UsLw[ub + 4];
                mma_bf16(Dhh[j], ah0, ah1, ah2, ah3, bh0, bh1);
                mma_bf16(Dhl[j], ah0, ah1, ah2, ah3, bl0, bl1);
                mma_bf16(Dlh[j], al0, al1, al2, al3, bh0, bh1);
            }
        }

        float D[3][4];
#pragma unroll
        for (int j = 0; j < 3; j++)
#pragma unroll
            for (int q = 0; q < 4; q++)
                D[j][q] = Dhh[j][q] + Dhl[j][q] + Dlh[j][q];

        if (kh > 0) {
#pragma unroll
            for (int j = 0; j < 3; j++) {
                int cc = j*8 + gc*2;
                *(float2*)&psum[((kh-1)*32 + r0)*24 + cc] = make_float2(D[j][0], D[j][1]);
                *(float2*)&psum[((kh-1)*32 + r1)*24 + cc] = make_float2(D[j][2], D[j][3]);
            }
        }
        __syncthreads();
        if (kh == 0) {
#pragma unroll
            for (int s = 0; s < 3; s++)
#pragma unroll
                for (int j = 0; j < 3; j++) {
                    int cc = j*8 + gc*2;
                    float2 p0 = *(const float2*)&psum[(s*32 + r0)*24 + cc];
                    float2 p1 = *(const float2*)&psum[(s*32 + r1)*24 + cc];
                    D[j][0] += p0.x; D[j][1] += p0.y;
                    D[j][2] += p1.x; D[j][3] += p1.y;
                }
#pragma unroll
            for (int j = 0; j < 3; j++) {
                int cc = j*8 + gc*2;
                *(float2*)&psum[r0*24 + cc] = make_float2(D[j][0], D[j][1]);
                *(float2*)&psum[r1*24 + cc] = make_float2(D[j][2], D[j][3]);
            }
        }
        __syncthreads();

        {
            float hz = psum[eb*24 + 0  + eu] + brz;
            float hr = psum[eb*24 + 8  + eu] + brr;
            float hh = psum[eb*24 + 16 + eu] + brh;

            float z    = __fdividef(1.f, 1.f + __expf(-(xz + hz)));
            float r    = __fdividef(1.f, 1.f + __expf(-(xr + hr)));
            float ta   = xh + r * hh;
            float cand = 1.f - __fdividef(2.f, __expf(2.f * ta) + 1.f);
            float hp   = joinhl(hsH[eb * HSTR + u0 + eu], hsL[eb * HSTR + u0 + eu]);
            float hn   = z * hp + (1.f - z) * cand;
            if (!mt) hn = hp;

            unsigned short hnh, hnl;
            split2(hn, hnh, hnl);
            g_hh[d][buf ^ 1][eb][u0 + eu] = hnh;
            g_hl[d][buf ^ 1][eb][u0 + eu] = hnl;
            out[((size_t)eb * TT + t) * (2*UU) + (size_t)d * UU + u0 + eu] = hn;
        }

        if (ts + 1 < TT) {
            __syncthreads();
            if (tid == 0) {
                __threadfence();
                atomicAdd(&g_cnt[d][ts], 1u);
                volatile unsigned* c = &g_cnt[d][ts];
                while (*c < NBLK) { }
                __threadfence();
            }
            __syncthreads();
        }
    }
}

// ---------------- launch --------------------------------------------------------
extern "C" void kernel_launch(void* const* d_in, const int* in_sizes, int n_in,
                              void* d_out, int out_size)
{
    const int*   tokens   = (const int*)  d_in[0];
    const float* emb      = (const float*)d_in[1];
    const float* W_fw     = (const float*)d_in[2];
    const float* U_fw     = (const float*)d_in[3];
    const float* b_in_fw  = (const float*)d_in[4];
    const float* b_rec_fw = (const float*)d_in[5];
    const float* W_bw     = (const float*)d_in[6];
    const float* U_bw     = (const float*)d_in[7];
    const float* b_in_bw  = (const float*)d_in[8];
    const float* b_rec_bw = (const float*)d_in[9];
    float* out = (float*)d_out;

    void* p;
    cudaGetSymbolAddress(&p, g_hh);
    cudaMemsetAsync(p, 0, sizeof(g_hh));
    cudaGetSymbolAddress(&p, g_hl);
    cudaMemsetAsync(p, 0, sizeof(g_hl));
    cudaGetSymbolAddress(&p, g_cnt);
    cudaMemsetAsync(p, 0, sizeof(g_cnt));

    prep_kernel<<<8000, 256>>>(tokens, emb);
    wprep_kernel<<<(2 * EE * U3) / 256, 256>>>(W_fw, W_bw);

    void* gxp;
    cudaGetSymbolAddress(&gxp, g_xproj);
    cudaFuncSetAttribute(xproj_kernel,
                         cudaFuncAttributeMaxDynamicSharedMemorySize, XSMEM_BYTES);
    dim3 gA(U3 / 64, (BB * TT) / 128, 2);
    xproj_kernel<<<gA, 256, XSMEM_BYTES>>>(tokens, b_in_fw, b_in_bw, (float*)gxp);

    cudaFuncSetAttribute(gru_r11,
                         cudaFuncAttributeMaxDynamicSharedMemorySize, SMEM_R11);
    gru_r11<<<RGRID, 256, SMEM_R11>>>(U_fw, b_rec_fw, U_bw, b_rec_bw, out);
}

// round 17
// speedup vs baseline: 1.2616x; 1.0067x over previous
#include <cuda_runtime.h>
#include <cuda_bf16.h>
#include <math.h>
#include <stdint.h>

#define BB 32
#define TT 512
#define EE 256
#define UU 512
#define U3 1536
#define NBLK 64
#define RGRID (2*NBLK)
#define HSTR 520         // gru SMEM ushort stride
#define ASTR 40          // xproj SMEM ushort stride (20 words)

// ---------------- device scratch ---------------------------------------------
__device__ unsigned short g_embh[(size_t)32000 * EE];
__device__ unsigned short g_embl[(size_t)32000 * EE];
__device__ unsigned short g_WTh[2][(size_t)U3 * EE];   // W^T split hi [d][n][k]
__device__ unsigned short g_WTl[2][(size_t)U3 * EE];   // W^T split lo
__device__ int            g_tokT[TT * BB];
__device__ unsigned short g_hh[2][2][BB][UU];
__device__ unsigned short g_hl[2][2][BB][UU];
__device__ unsigned       g_cnt[2][TT];
__device__ float          g_xproj[2][BB][TT][U3];

// ---------------- bf16 helpers -------------------------------------------------
__device__ __forceinline__ unsigned short bf16_hi(float v) {
    return __bfloat16_as_ushort(__float2bfloat16_rn(v));
}
__device__ __forceinline__ void split2(float v, unsigned short& h, unsigned short& l) {
    h = bf16_hi(v);
    float fh = __uint_as_float((unsigned)h << 16);
    l = bf16_hi(v - fh);
}
__device__ __forceinline__ float joinhl(unsigned short h, unsigned short l) {
    return __uint_as_float((unsigned)h << 16) + __uint_as_float((unsigned)l << 16);
}
__device__ __forceinline__ void mma_bf16(float* D,
                                         unsigned a0, unsigned a1, unsigned a2, unsigned a3,
                                         unsigned b0, unsigned b1) {
    asm volatile(
        "mma.sync.aligned.m16n8k16.row.col.f32.bf16.bf16.f32 "
        "{%0,%1,%2,%3}, {%4,%5,%6,%7}, {%8,%9}, {%0,%1,%2,%3};"
        : "+f"(D[0]), "+f"(D[1]), "+f"(D[2]), "+f"(D[3])
        : "r"(a0), "r"(a1), "r"(a2), "r"(a3), "r"(b0), "r"(b1));
}
__device__ __forceinline__ void cp16(void* dst, const void* src) {
    unsigned daddr = (unsigned)__cvta_generic_to_shared(dst);
    asm volatile("cp.async.cg.shared.global [%0], [%1], 16;" :: "r"(daddr), "l"(src));
}

// ---------------- prep 1: split emb + transpose tokens -------------------------
__global__ void __launch_bounds__(256) prep_kernel(
    const int* __restrict__ tokens, const float* __restrict__ emb)
{
    int gid = blockIdx.x * 256 + threadIdx.x;
    size_t base = (size_t)gid * 4;
    float4 v = *(const float4*)(emb + base);
    unsigned short h, l;
    split2(v.x, h, l); g_embh[base+0] = h; g_embl[base+0] = l;
    split2(v.y, h, l); g_embh[base+1] = h; g_embl[base+1] = l;
    split2(v.z, h, l); g_embh[base+2] = h; g_embl[base+2] = l;
    split2(v.w, h, l); g_embh[base+3] = h; g_embl[base+3] = l;
    if (gid < BB * TT) {
        int b = gid >> 9, t = gid & 511;
        g_tokT[t * 32 + b] = tokens[gid];
    }
}

// ---------------- prep 2: split + transpose W -----------------------------------
__global__ void __launch_bounds__(256) wprep_kernel(
    const float* __restrict__ W_fw, const float* __restrict__ W_bw)
{
    int gid = blockIdx.x * 256 + threadIdx.x;          // < 2*256*1536
    int d = gid / (EE * U3);
    int r = gid - d * (EE * U3);
    int k = r / U3;
    int n = r - k * U3;
    float v = (d ? W_bw : W_fw)[r];
    unsigned short h, l;
    split2(v, h, l);
    g_WTh[d][(size_t)n * EE + k] = h;
    g_WTl[d][(size_t)n * EE + k] = l;
}

// ---------------- Kernel A: xproj, BM=128 BN=128 BK=32, cp.async 2-stage --------
// A bufs: 2 x 128 x 40 ushorts per array (hi/lo); B bufs: 2 x 128 x 40 per array.
#define XSMEM_USH (4 * 2 * 128 * ASTR)
#define XSMEM_BYTES (XSMEM_USH * 2)

__global__ void __launch_bounds__(256) xproj_kernel(
    const int* __restrict__ tokens,
    const float* __restrict__ b_in_fw, const float* __restrict__ b_in_bw,
    float* __restrict__ gx)
{
    extern __shared__ unsigned short xs[];
    unsigned short* SAh = xs;                   // [2][128*40]
    unsigned short* SAl = SAh + 2*5120;
    unsigned short* SBh = SAl + 2*5120;         // [2][128*40]
    unsigned short* SBl = SBh + 2*5120;
    __shared__ int toks[128];

    const int d  = blockIdx.z;
    const float* __restrict__ bp = d ? b_in_bw : b_in_fw;
    const unsigned short* WTh = g_WTh[d];
    const unsigned short* WTl = g_WTl[d];
    const int n0 = blockIdx.x * 128;
    const int m0 = blockIdx.y * 128;
    const int tid = threadIdx.x;
    const int wid = tid >> 5;
    const int lane = tid & 31;
    const int gr = lane >> 2;
    const int gc = lane & 3;

    if (tid < 128) toks[tid] = tokens[m0 + tid];
    __syncthreads();

    const unsigned* SAhw = (const unsigned*)SAh;
    const unsigned* SAlw = (const unsigned*)SAl;
    const unsigned* SBhw = (const unsigned*)SBh;
    const unsigned* SBlw = (const unsigned*)SBl;

    float D[16][4];
#pragma unroll
    for (int j = 0; j < 16; j++)
#pragma unroll
        for (int q = 0; q < 4; q++) D[j][q] = 0.f;

    const int baseA0 = (wid * 16 + gr) * (ASTR/2);
    const int baseA1 = baseA0 + 8 * (ASTR/2);

    auto stage = [&](int bf, int k0) {
        int off = bf * 5120;
#pragma unroll
        for (int i = 0; i < 4; i++) {
            int uid = tid + i * 256;             // 0..1023
            int row = uid >> 3;
            int rem = uid & 7;
            int arr = rem >> 2;
            int ch  = rem & 3;
            const unsigned short* src =
                (arr ? g_embl : g_embh) + (size_t)toks[row] * EE + k0 + ch * 8;
            unsigned short* dst = (arr ? SAl : SAh) + off + row * ASTR + ch * 8;
            cp16(dst, src);
        }
#pragma unroll
        for (int i = 0; i < 4; i++) {
            int uid = tid + i * 256;             // 0..1023
            int col = uid >> 3;
            int rem = uid & 7;
            int arr = rem >> 2;
            int ch  = rem & 3;
            const unsigned short* src =
                (arr ? WTl : WTh) + (size_t)(n0 + col) * EE + k0 + ch * 8;
            unsigned short* dst = (arr ? SBl : SBh) + off + col * ASTR + ch * 8;
            cp16(dst, src);
        }
        asm volatile("cp.async.commit_group;" ::: "memory");
    };

    stage(0, 0);

    for (int it = 0; it < 8; it++) {
        if (it < 7) {
            stage((it + 1) & 1, (it + 1) * 32);
            asm volatile("cp.async.wait_group 1;" ::: "memory");
        } else {
            asm volatile("cp.async.wait_group 0;" ::: "memory");
        }
        __syncthreads();

        const int bufw = (it & 1) * 2560;        // word offset into either buffer
#pragma unroll
        for (int kt = 0; kt < 2; kt++) {
            int kw = kt * 8;
            unsigned ah0 = SAhw[bufw + baseA0 + kw + gc];
            unsigned ah1 = SAhw[bufw + baseA1 + kw + gc];
            unsigned ah2 = SAhw[bufw + baseA0 + kw + gc + 4];
            unsigned ah3 = SAhw[bufw + baseA1 + kw + gc + 4];
            unsigned al0 = SAlw[bufw + baseA0 + kw + gc];
            unsigned al1 = SAlw[bufw + baseA1 + kw + gc];
            unsigned al2 = SAlw[bufw + baseA0 + kw + gc + 4];
            unsigned al3 = SAlw[bufw + baseA1 + kw + gc + 4];
#pragma unroll
            for (int j = 0; j < 16; j++) {
                int ub = bufw + (j * 8 + gr) * (ASTR/2) + kw + gc;
                unsigned bh0 = SBhw[ub], bh1 = SBhw[ub + 4];
                unsigned bl0 = SBlw[ub], bl1 = SBlw[ub + 4];
                mma_bf16(D[j], ah0, ah1, ah2, ah3, bh0, bh1);
                mma_bf16(D[j], ah0, ah1, ah2, ah3, bl0, bl1);
                mma_bf16(D[j], al0, al1, al2, al3, bh0, bh1);
            }
        }
        __syncthreads();
    }

    const size_t mbase = (size_t)d * (BB*TT) + m0 + wid * 16;
#pragma unroll
    for (int j = 0; j < 16; j++) {
        int cc = n0 + j * 8 + gc * 2;
        float2 bias = *(const float2*)(bp + cc);
        float2 vlo = { D[j][0] + bias.x, D[j][1] + bias.y };
        float2 vhi = { D[j][2] + bias.x, D[j][3] + bias.y };
        *(float2*)(gx + (mbase + gr)     * U3 + cc) = vlo;
        *(float2*)(gx + (mbase + gr + 8) * U3 + cc) = vhi;
    }
}

// ---------------- Kernel B: persistent GRU (verified; out-store deferred) ------
#define SMEM_R11 ((32*HSTR*2 + 24*HSTR*2) * 2 + 3*32*24*4 + 64)

__global__ void __launch_bounds__(256, 1) gru_r11(
    const float* __restrict__ U_fw, const float* __restrict__ b_rec_fw,
    const float* __restrict__ U_bw, const float* __restrict__ b_rec_bw,
    float* __restrict__ out)
{
    extern __shared__ unsigned short smemus[];
    unsigned short* hsH = smemus;
    unsigned short* hsL = hsH + 32*HSTR;
    unsigned short* UsH = hsL + 32*HSTR;
    unsigned short* UsL = UsH + 24*HSTR;
    float* psum = (float*)(UsL + 24*HSTR);

    const unsigned* hsHw = (const unsigned*)hsH;
    const unsigned* hsLw = (const unsigned*)hsL;
    const unsigned* UsHw = (const unsigned*)UsH;
    const unsigned* UsLw = (const unsigned*)UsL;

    const int bid = blockIdx.x;
    const int d   = bid >> 6;
    const int jb  = bid & (NBLK - 1);
    const int u0  = jb * 8;
    const int tid = threadIdx.x;
    const int wid = tid >> 5;
    const int lane = tid & 31;
    const int mi = wid & 1;
    const int kh = wid >> 1;
    const int gr = lane >> 2;
    const int gc = lane & 3;

    const float* __restrict__ Uw = d ? U_bw : U_fw;
    const float* __restrict__ br = d ? b_rec_bw : b_rec_fw;

    for (int idx = tid; idx < 24 * 512; idx += 256) {
        int c = idx >> 9;
        int k = idx & 511;
        int g = c >> 3;
        float v = Uw[(size_t)k * U3 + g * 512 + u0 + (c & 7)];
        unsigned short h, l;
        split2(v, h, l);
        UsH[c * HSTR + k] = h;
        UsL[c * HSTR + k] = l;
    }

    const int eb = tid >> 3, eu = tid & 7;
    const float brz = br[0*512 + u0 + eu];
    const float brr = br[1*512 + u0 + eu];
    const float brh = br[2*512 + u0 + eu];

    const float* gx = &g_xproj[0][0][0][0];

    const int base0 = (mi*16 + gr) * (HSTR/2);
    const int base1 = base0 + 8 * (HSTR/2);
    const int r0  = mi*16 + gr;
    const int r1  = r0 + 8;
    const int kwbase = kh * 64;
    const int srow = mi * 16;
    const int sk   = kh * 128;

    __syncthreads();

    for (int ts = 0; ts < TT; ts++) {
        const int t   = d ? (TT - 1 - ts) : ts;
        const int buf = ts & 1;

        size_t xb = ((size_t)d * (BB*TT) + (size_t)eb * TT + t) * U3;
        float xz = gx[xb + u0 + eu];
        float xr = gx[xb + 512 + u0 + eu];
        float xh = gx[xb + 1024 + u0 + eu];
        int   mt = (g_tokT[t * 32 + eb] != 0);

#pragma unroll
        for (int i = 0; i < 8; i++) {
            int uid = lane + 32 * i;
            int row = srow + (uid >> 4);
            int col = uid & 15;
            uint4 vH = __ldcg((const uint4*)&g_hh[d][buf][row][sk] + col);
            uint4 vL = __ldcg((const uint4*)&g_hl[d][buf][row][sk] + col);
            *(uint4*)&hsH[row * HSTR + sk + col * 8] = vH;
            *(uint4*)&hsL[row * HSTR + sk + col * 8] = vL;
        }
        __syncwarp();

        float Dhh[3][4], Dhl[3][4], Dlh[3][4];
#pragma unroll
        for (int j = 0; j < 3; j++)
#pragma unroll
            for (int q = 0; q < 4; q++) { Dhh[j][q] = 0.f; Dhl[j][q] = 0.f; Dlh[j][q] = 0.f; }

#pragma unroll 2
        for (int kt = 0; kt < 8; kt++) {
            int kw = kwbase + kt * 8;
            unsigned ah0 = hsHw[base0 + kw + gc];
            unsigned ah1 = hsHw[base1 + kw + gc];
            unsigned ah2 = hsHw[base0 + kw + gc + 4];
            unsigned ah3 = hsHw[base1 + kw + gc + 4];
            unsigned al0 = hsLw[base0 + kw + gc];
            unsigned al1 = hsLw[base1 + kw + gc];
            unsigned al2 = hsLw[base0 + kw + gc + 4];
            unsigned al3 = hsLw[base1 + kw + gc + 4];
#pragma unroll
            for (int j = 0; j < 3; j++) {
                int ub = (j*8 + gr) * (HSTR/2) + kw + gc;
                unsigned bh0 = UsHw[ub], bh1 = UsHw[ub + 4];
                unsigned bl0 = UsLw[ub], bl1 = UsLw[ub + 4];
                mma_bf16(Dhh[j], ah0, ah1, ah2, ah3, bh0, bh1);
                mma_bf16(Dhl[j], ah0, ah1, ah2, ah3, bl0, bl1);
                mma_bf16(Dlh[j], al0, al1, al2, al3, bh0, bh1);
            }
        }

        float D[3][4];
#pragma unroll
        for (int j = 0; j < 3; j++)
#pragma unroll
            for (int q = 0; q < 4; q++)
                D[j][q] = Dhh[j][q] + Dhl[j][q] + Dlh[j][q];

        if (kh > 0) {
#pragma unroll
            for (int j = 0; j < 3; j++) {
                int cc = j*8 + gc*2;
                *(float2*)&psum[((kh-1)*32 + r0)*24 + cc] = make_float2(D[j][0], D[j][1]);
                *(float2*)&psum[((kh-1)*32 + r1)*24 + cc] = make_float2(D[j][2], D[j][3]);
            }
        }
        __syncthreads();
        if (kh == 0) {
#pragma unroll
            for (int s = 0; s < 3; s++)
#pragma unroll
                for (int j = 0; j < 3; j++) {
                    int cc = j*8 + gc*2;
                    float2 p0 = *(const float2*)&psum[(s*32 + r0)*24 + cc];
                    float2 p1 = *(const float2*)&psum[(s*32 + r1)*24 + cc];
                    D[j][0] += p0.x; D[j][1] += p0.y;
                    D[j][2] += p1.x; D[j][3] += p1.y;
                }
#pragma unroll
            for (int j = 0; j < 3; j++) {
                int cc = j*8 + gc*2;
                *(float2*)&psum[r0*24 + cc] = make_float2(D[j][0], D[j][1]);
                *(float2*)&psum[r1*24 + cc] = make_float2(D[j][2], D[j][3]);
            }
        }
        __syncthreads();

        float hn;
        {
            float hz = psum[eb*24 + 0  + eu] + brz;
            float hr = psum[eb*24 + 8  + eu] + brr;
            float hh = psum[eb*24 + 16 + eu] + brh;

            float z    = __fdividef(1.f, 1.f + __expf(-(xz + hz)));
            float r    = __fdividef(1.f, 1.f + __expf(-(xr + hr)));
            float ta   = xh + r * hh;
            float cand = 1.f - __fdividef(2.f, __expf(2.f * ta) + 1.f);
            float hp   = joinhl(hsH[eb * HSTR + u0 + eu], hsL[eb * HSTR + u0 + eu]);
            hn = z * hp + (1.f - z) * cand;
            if (!mt) hn = hp;

            unsigned short hnh, hnl;
            split2(hn, hnh, hnl);
            g_hh[d][buf ^ 1][eb][u0 + eu] = hnh;
            g_hl[d][buf ^ 1][eb][u0 + eu] = hnl;
        }

        if (ts + 1 < TT) {
            __syncthreads();
            if (tid == 0) {
                __threadfence();
                atomicAdd(&g_cnt[d][ts], 1u);
                volatile unsigned* c = &g_cnt[d][ts];
                while (*c < NBLK) { }
                __threadfence();
            }
            __syncthreads();
        }

        // out store deferred past the barrier: not on the release-fence path
        out[((size_t)eb * TT + t) * (2*UU) + (size_t)d * UU + u0 + eu] = hn;
    }
}

// ---------------- launch --------------------------------------------------------
extern "C" void kernel_launch(void* const* d_in, const int* in_sizes, int n_in,
                              void* d_out, int out_size)
{
    const int*   tokens   = (const int*)  d_in[0];
    const float* emb      = (const float*)d_in[1];
    const float* W_fw     = (const float*)d_in[2];
    const float* U_fw     = (const float*)d_in[3];
    const float* b_in_fw  = (const float*)d_in[4];
    const float* b_rec_fw = (const float*)d_in[5];
    const float* W_bw     = (const float*)d_in[6];
    const float* U_bw     = (const float*)d_in[7];
    const float* b_in_bw  = (const float*)d_in[8];
    const float* b_rec_bw = (const float*)d_in[9];
    float* out = (float*)d_out;

    void* p;
    cudaGetSymbolAddress(&p, g_hh);
    cudaMemsetAsync(p, 0, sizeof(g_hh));
    cudaGetSymbolAddress(&p, g_hl);
    cudaMemsetAsync(p, 0, sizeof(g_hl));
    cudaGetSymbolAddress(&p, g_cnt);
    cudaMemsetAsync(p, 0, sizeof(g_cnt));

    prep_kernel<<<8000, 256>>>(tokens, emb);
    wprep_kernel<<<(2 * EE * U3) / 256, 256>>>(W_fw, W_bw);

    void* gxp;
    cudaGetSymbolAddress(&gxp, g_xproj);
    cudaFuncSetAttribute(xproj_kernel,
                         cudaFuncAttributeMaxDynamicSharedMemorySize, XSMEM_BYTES);
    dim3 gA(U3 / 128, (BB * TT) / 128, 2);
    xproj_kernel<<<gA, 256, XSMEM_BYTES>>>(tokens, b_in_fw, b_in_bw, (float*)gxp);

    cudaFuncSetAttribute(gru_r11,
                         cudaFuncAttributeMaxDynamicSharedMemorySize, SMEM_R11);
    gru_r11<<<RGRID, 256, SMEM_R11>>>(U_fw, b_rec_fw, U_bw, b_rec_bw, out);
}